// round 4
// baseline (speedup 1.0000x reference)
#include <cuda_runtime.h>
#include <math.h>

#define N    64
#define LD   65            // padded leading dim in shared (bank-conflict free columns)
#define NT   256           // threads per block
#define TILE (N*LD)        // floats per shared buffer
#define MAXB 8192

// ----------------------------------------------------------------------------
// Global scratch (static __device__ arrays: no allocation in kernel_launch)
// ----------------------------------------------------------------------------
__device__ float g_M  [N*N];
__device__ float g_Ms [N*N];
__device__ float g_Mis[N*N];
__device__ float g_L  [N*N];
__device__ float g_C  [N*N];
__device__ float g_VM [N*N];                 // warm-start eigvecs of M
__device__ float g_scratch[(size_t)MAXB*N*N];  // per-matrix logm (134 MB)
__device__ float g_Vw     [(size_t)MAXB*N*N];  // per-matrix eigvec warm start (134 MB)
__device__ float g_partial[(MAXB/32)*N*N];     // reduction partials (4 MB)

// ----------------------------------------------------------------------------
// Block-cooperative helpers (blockDim.x == NT). Convention: every helper ends
// with __syncthreads(), and assumes its inputs are ready on entry.
// ----------------------------------------------------------------------------
__device__ __forceinline__ void g2s(float* S, const float* __restrict__ G) {
    for (int idx = threadIdx.x; idx < N*N; idx += NT)
        S[(idx >> 6) * LD + (idx & 63)] = G[idx];
    __syncthreads();
}
__device__ __forceinline__ void s2g(float* __restrict__ G, const float* S) {
    for (int idx = threadIdx.x; idx < N*N; idx += NT)
        G[idx] = S[(idx >> 6) * LD + (idx & 63)];
    __syncthreads();
}
__device__ __forceinline__ void set_identity(float* S) {
    for (int idx = threadIdx.x; idx < N*N; idx += NT) {
        int i = idx >> 6, j = idx & 63;
        S[i * LD + j] = (i == j) ? 1.0f : 0.0f;
    }
    __syncthreads();
}
__device__ __forceinline__ void symmetrize(float* A) {
    for (int idx = threadIdx.x; idx < N*N; idx += NT) {
        int i = idx >> 6, j = idx & 63;
        if (i < j) {
            float t = 0.5f * (A[i*LD + j] + A[j*LD + i]);
            A[i*LD + j] = t;
            A[j*LD + i] = t;
        }
    }
    __syncthreads();
}

// D = A * B   (all shared, 64x64, LD-padded). D must not alias A or B.
__device__ __forceinline__ void gemm_nn(float* D, const float* A, const float* B) {
    const int tx = (threadIdx.x & 15) << 2;
    const int ty = (threadIdx.x >> 4) << 2;
    float acc[4][4] = {};
#pragma unroll 8
    for (int k = 0; k < N; ++k) {
        float a0 = A[(ty+0)*LD + k], a1 = A[(ty+1)*LD + k];
        float a2 = A[(ty+2)*LD + k], a3 = A[(ty+3)*LD + k];
        float b0 = B[k*LD + tx+0], b1 = B[k*LD + tx+1];
        float b2 = B[k*LD + tx+2], b3 = B[k*LD + tx+3];
        acc[0][0] += a0*b0; acc[0][1] += a0*b1; acc[0][2] += a0*b2; acc[0][3] += a0*b3;
        acc[1][0] += a1*b0; acc[1][1] += a1*b1; acc[1][2] += a1*b2; acc[1][3] += a1*b3;
        acc[2][0] += a2*b0; acc[2][1] += a2*b1; acc[2][2] += a2*b2; acc[2][3] += a2*b3;
        acc[3][0] += a3*b0; acc[3][1] += a3*b1; acc[3][2] += a3*b2; acc[3][3] += a3*b3;
    }
#pragma unroll
    for (int r = 0; r < 4; ++r)
#pragma unroll
        for (int c = 0; c < 4; ++c)
            D[(ty+r)*LD + tx + c] = acc[r][c];
    __syncthreads();
}

// D = A^T * B
__device__ __forceinline__ void gemm_tn(float* D, const float* A, const float* B) {
    const int tx = (threadIdx.x & 15) << 2;
    const int ty = (threadIdx.x >> 4) << 2;
    float acc[4][4] = {};
#pragma unroll 8
    for (int k = 0; k < N; ++k) {
        float a0 = A[k*LD + ty+0], a1 = A[k*LD + ty+1];
        float a2 = A[k*LD + ty+2], a3 = A[k*LD + ty+3];
        float b0 = B[k*LD + tx+0], b1 = B[k*LD + tx+1];
        float b2 = B[k*LD + tx+2], b3 = B[k*LD + tx+3];
        acc[0][0] += a0*b0; acc[0][1] += a0*b1; acc[0][2] += a0*b2; acc[0][3] += a0*b3;
        acc[1][0] += a1*b0; acc[1][1] += a1*b1; acc[1][2] += a1*b2; acc[1][3] += a1*b3;
        acc[2][0] += a2*b0; acc[2][1] += a2*b1; acc[2][2] += a2*b2; acc[2][3] += a2*b3;
        acc[3][0] += a3*b0; acc[3][1] += a3*b1; acc[3][2] += a3*b2; acc[3][3] += a3*b3;
    }
#pragma unroll
    for (int r = 0; r < 4; ++r)
#pragma unroll
        for (int c = 0; c < 4; ++c)
            D[(ty+r)*LD + tx + c] = acc[r][c];
    __syncthreads();
}

// D = A * B^T
__device__ __forceinline__ void gemm_nt(float* D, const float* A, const float* B) {
    const int tx = (threadIdx.x & 15) << 2;
    const int ty = (threadIdx.x >> 4) << 2;
    float acc[4][4] = {};
#pragma unroll 8
    for (int k = 0; k < N; ++k) {
        float a0 = A[(ty+0)*LD + k], a1 = A[(ty+1)*LD + k];
        float a2 = A[(ty+2)*LD + k], a3 = A[(ty+3)*LD + k];
        float b0 = B[(tx+0)*LD + k], b1 = B[(tx+1)*LD + k];
        float b2 = B[(tx+2)*LD + k], b3 = B[(tx+3)*LD + k];
        acc[0][0] += a0*b0; acc[0][1] += a0*b1; acc[0][2] += a0*b2; acc[0][3] += a0*b3;
        acc[1][0] += a1*b0; acc[1][1] += a1*b1; acc[1][2] += a1*b2; acc[1][3] += a1*b3;
        acc[2][0] += a2*b0; acc[2][1] += a2*b1; acc[2][2] += a2*b2; acc[2][3] += a2*b3;
        acc[3][0] += a3*b0; acc[3][1] += a3*b1; acc[3][2] += a3*b2; acc[3][3] += a3*b3;
    }
#pragma unroll
    for (int r = 0; r < 4; ++r)
#pragma unroll
        for (int c = 0; c < 4; ++c)
            D[(ty+r)*LD + tx + c] = acc[r][c];
    __syncthreads();
}

// D = V * diag(f(diag(A))).  mode: 0=log, 1=exp, 2=sqrt, 3=1/sqrt
__device__ __forceinline__ void colscale(float* D, const float* V, const float* A, int mode) {
    __shared__ float f[64];
    if (threadIdx.x < 64) {
        float d = A[threadIdx.x * LD + threadIdx.x];
        float v;
        if      (mode == 0) v = logf(fmaxf(d, 1e-30f));
        else if (mode == 1) v = expf(d);
        else if (mode == 2) v = sqrtf(fmaxf(d, 0.0f));
        else                v = 1.0f / sqrtf(fmaxf(d, 1e-30f));
        f[threadIdx.x] = v;
    }
    __syncthreads();
    for (int idx = threadIdx.x; idx < N*N; idx += NT) {
        int i = idx >> 6, k = idx & 63;
        D[i*LD + k] = V[i*LD + k] * f[k];
    }
    __syncthreads();
}

// ----------------------------------------------------------------------------
// Parallel cyclic Jacobi eigensolver: A (symmetric, LD-padded shared) is
// diagonalized in place; V accumulates rotations (A_in = V D V^T on exit,
// with D = diag(A_out)). Early exit on off-diag Frobenius convergence.
// ----------------------------------------------------------------------------
__device__ void jacobi(float* A, float* V) {
    __shared__ float s_c[32], s_s[32];
    __shared__ int   s_p[32], s_q[32];
    __shared__ float s_red[16];
    __shared__ int   s_go;
    const int tid   = threadIdx.x;
    const int lane6 = tid & 63;   // row/col owned in update phases
    const int pb    = tid >> 6;   // pair-group base (0..3)

    for (int sweep = 0; sweep < 16; ++sweep) {
        // --- convergence check (fixed-order deterministic reduction) ---
        float off = 0.0f, tot = 0.0f;
        for (int idx = tid; idx < N*N; idx += NT) {
            int i = idx >> 6, j = idx & 63;
            float v = A[i*LD + j], v2 = v * v;
            tot += v2;
            if (i != j) off += v2;
        }
#pragma unroll
        for (int o = 16; o > 0; o >>= 1) {
            off += __shfl_down_sync(0xffffffffu, off, o);
            tot += __shfl_down_sync(0xffffffffu, tot, o);
        }
        if ((tid & 31) == 0) { s_red[tid >> 5] = off; s_red[8 + (tid >> 5)] = tot; }
        __syncthreads();
        if (tid == 0) {
            float o = 0.0f, t = 0.0f;
            for (int w = 0; w < 8; ++w) { o += s_red[w]; t += s_red[8 + w]; }
            s_go = (o > 1e-10f * t) ? 1 : 0;
        }
        __syncthreads();
        if (!s_go) break;

        // --- one sweep: 63 rounds of 32 disjoint rotations ---
        for (int r = 0; r < 63; ++r) {
            if (tid < 32) {
                int i = tid, p, q;
                if (i == 0) { p = 63; q = r; }
                else        { p = (r + i) % 63; q = (r + 63 - i) % 63; }
                if (p > q) { int t2 = p; p = q; q = t2; }
                float app = A[p*LD + p], aqq = A[q*LD + q], apq = A[p*LD + q];
                float c = 1.0f, s = 0.0f;
                if (fabsf(apq) > 1e-32f) {
                    float tau = (aqq - app) / (2.0f * apq);
                    float t   = copysignf(1.0f, tau) / (fabsf(tau) + sqrtf(1.0f + tau * tau));
                    c = 1.0f / sqrtf(1.0f + t * t);
                    s = t * c;
                }
                s_p[i] = p; s_q[i] = q; s_c[i] = c; s_s[i] = s;
            }
            __syncthreads();
            // column phase: A <- A * J  (each thread: fixed row, 8 pairs)
#pragma unroll
            for (int w = 0; w < 8; ++w) {
                int pi = pb + 4 * w;
                int p = s_p[pi], q = s_q[pi];
                float c = s_c[pi], s = s_s[pi];
                float x = A[lane6*LD + p], y = A[lane6*LD + q];
                A[lane6*LD + p] = c * x - s * y;
                A[lane6*LD + q] = s * x + c * y;
            }
            __syncthreads();
            // row phase: A <- J^T * A  (each thread: fixed col, 8 pairs)
#pragma unroll
            for (int w = 0; w < 8; ++w) {
                int pi = pb + 4 * w;
                int p = s_p[pi], q = s_q[pi];
                float c = s_c[pi], s = s_s[pi];
                float x = A[p*LD + lane6], y = A[q*LD + lane6];
                A[p*LD + lane6] = c * x - s * y;
                A[q*LD + lane6] = s * x + c * y;
            }
            // V phase: V <- V * J (independent of row phase: no extra sync)
#pragma unroll
            for (int w = 0; w < 8; ++w) {
                int pi = pb + 4 * w;
                int p = s_p[pi], q = s_q[pi];
                float c = s_c[pi], s = s_s[pi];
                float x = V[lane6*LD + p], y = V[lane6*LD + q];
                V[lane6*LD + p] = c * x - s * y;
                V[lane6*LD + q] = s * x + c * y;
            }
            __syncthreads();
        }
    }
    __syncthreads();
}

// ----------------------------------------------------------------------------
// Kernels
// ----------------------------------------------------------------------------

// Stage-1 reduction: each block sums 32 consecutive matrices of src.
__global__ void __launch_bounds__(NT) reduce32_kernel(const float* __restrict__ src,
                                                      float* __restrict__ dst, int Bsz) {
    int j = blockIdx.x;
    int b0 = j * 32;
    int cnt = min(32, Bsz - b0);
    for (int i = threadIdx.x; i < N*N; i += NT) {
        float a = 0.0f;
        for (int k = 0; k < cnt; ++k)
            a += src[(size_t)(b0 + k) * (N*N) + i];
        dst[(size_t)j * (N*N) + i] = a;
    }
}

// Stage-2: dst[i] = scale * sum_j part[j][i].  Launch <<<16, 256>>>.
__global__ void __launch_bounds__(NT) reduceFinal_kernel(const float* __restrict__ part,
                                                         float* __restrict__ dst,
                                                         int nb, float scale) {
    int i = blockIdx.x * NT + threadIdx.x;
    float a = 0.0f;
    for (int j = 0; j < nb; ++j)
        a += part[(size_t)j * (N*N) + i];
    dst[i] = a * scale;
}

// eigh(M) -> Ms = sqrtm(M), Mis = invsqrtm(M). Warm-starts from g_VM.
__global__ void __launch_bounds__(NT) prep_M_kernel(int warm) {
    extern __shared__ float sm[];
    float *b0 = sm, *b1 = sm + TILE, *b2 = sm + 2*TILE, *b3 = sm + 3*TILE;
    g2s(b0, g_M);
    float *pA;
    if (warm) {
        g2s(b1, g_VM);
        gemm_nn(b2, b0, b1);   // M V
        gemm_tn(b3, b1, b2);   // V^T M V
        symmetrize(b3);
        pA = b3;
    } else {
        set_identity(b1);
        symmetrize(b0);
        pA = b0;
    }
    jacobi(pA, b1);
    s2g(g_VM, b1);
    colscale(b2, b1, pA, 2);   // V sqrt(d)
    gemm_nt(b3 == pA ? b0 : b3, b2, b1);
    s2g(g_Ms, b3 == pA ? b0 : b3);
    colscale(b2, b1, pA, 3);   // V / sqrt(d)
    gemm_nt(b3 == pA ? b0 : b3, b2, b1);
    s2g(g_Mis, b3 == pA ? b0 : b3);
}

// Per-matrix: Y = Mis X Mis; eigh(Y) (warm-started); logm -> g_scratch; V -> g_Vw.
__global__ void __launch_bounds__(NT) batch_log_kernel(const float* __restrict__ data, int warm) {
    extern __shared__ float sm[];
    float *b0 = sm, *b1 = sm + TILE, *b2 = sm + 2*TILE, *b3 = sm + 3*TILE;
    const size_t b = blockIdx.x;
    const float* X = data + b * (N*N);

    g2s(b1, g_Mis);
    g2s(b0, X);
    gemm_nn(b2, b1, b0);       // Mis X
    gemm_nn(b0, b2, b1);       // Y = Mis X Mis

    float* pA;
    if (warm) {
        g2s(b1, g_Vw + b * (N*N));   // previous eigvecs
        gemm_nn(b2, b0, b1);         // Y V
        gemm_tn(b3, b1, b2);         // V^T Y V  (near-diagonal)
        symmetrize(b3);
        pA = b3;
    } else {
        set_identity(b1);
        symmetrize(b0);
        pA = b0;
    }
    jacobi(pA, b1);
    s2g(g_Vw + b * (N*N), b1);

    colscale(b2, b1, pA, 0);         // V log(d)
    float* dst = (pA == b3) ? b3 : b3;   // b3 free (cold) or reusable (warm: diag consumed)
    gemm_nt(dst, b2, b1);            // logm(Y) = V log(d) V^T
    s2g(g_scratch + b * (N*N), dst);
}

// M <- sym(Ms expm(L) Ms)
__global__ void __launch_bounds__(NT) update_M_kernel() {
    extern __shared__ float sm[];
    float *b0 = sm, *b1 = sm + TILE, *b2 = sm + 2*TILE, *b3 = sm + 3*TILE;
    g2s(b0, g_L);
    set_identity(b1);
    symmetrize(b0);
    jacobi(b0, b1);
    colscale(b2, b1, b0, 1);   // V exp(d)
    gemm_nt(b3, b2, b1);       // E = expm(L)
    g2s(b0, g_Ms);
    gemm_nn(b2, b0, b3);       // Ms E
    gemm_nn(b1, b2, b0);       // Ms E Ms
    for (int idx = threadIdx.x; idx < N*N; idx += NT) {
        int i = idx >> 6, j = idx & 63;
        g_M[idx] = 0.5f * (b1[i*LD + j] + b1[j*LD + i]);
    }
}

// C = expm(0.25 (bias + bias^T)) * invsqrtm(M)
__global__ void __launch_bounds__(NT) final_prep_kernel(const float* __restrict__ bias) {
    extern __shared__ float sm[];
    float *b0 = sm, *b1 = sm + TILE, *b2 = sm + 2*TILE, *b3 = sm + 3*TILE;
    // W = invsqrtm(M), warm-started from g_VM
    g2s(b0, g_M);
    g2s(b1, g_VM);
    gemm_nn(b2, b0, b1);
    gemm_tn(b3, b1, b2);
    symmetrize(b3);
    jacobi(b3, b1);
    colscale(b2, b1, b3, 3);
    gemm_nt(b0, b2, b1);       // W -> b0
    // stash W in b3 (b3's diag consumed)
    for (int idx = threadIdx.x; idx < N*LD; idx += NT) b3[idx] = b0[idx];
    __syncthreads();
    // Bs = expm(0.25 (bias + bias^T))
    for (int idx = threadIdx.x; idx < N*N; idx += NT) {
        int i = idx >> 6, j = idx & 63;
        b0[i*LD + j] = 0.25f * (bias[i*N + j] + bias[j*N + i]);
    }
    __syncthreads();
    set_identity(b1);
    jacobi(b0, b1);
    colscale(b2, b1, b0, 1);
    gemm_nt(b0, b2, b1);       // Bs -> b0
    gemm_nn(b2, b0, b3);       // C = Bs W
    s2g(g_C, b2);
}

// out_b = C X_b C^T
__global__ void __launch_bounds__(NT) apply_kernel(const float* __restrict__ data,
                                                   float* __restrict__ out) {
    extern __shared__ float sm[];
    float *b0 = sm, *b1 = sm + TILE, *b2 = sm + 2*TILE, *b3 = sm + 3*TILE;
    const size_t b = blockIdx.x;
    g2s(b1, g_C);
    g2s(b0, data + b * (N*N));
    gemm_nn(b2, b1, b0);       // C X
    gemm_nt(b3, b2, b1);       // (C X) C^T
    s2g(out + b * (N*N), b3);
}

// ----------------------------------------------------------------------------
// Host launcher (graph-capturable: kernel launches + symbol/attr queries only)
// ----------------------------------------------------------------------------
extern "C" void kernel_launch(void* const* d_in, const int* in_sizes, int n_in,
                              void* d_out, int out_size) {
    const float* data = (const float*)d_in[0];
    const float* bias = (const float*)d_in[1];
    int sz0 = in_sizes[0], sz1 = (n_in > 1) ? in_sizes[1] : 0;
    if (sz0 == N*N && sz1 > N*N) {        // defensive input-order swap
        data = (const float*)d_in[1];
        bias = (const float*)d_in[0];
        int t = sz0; sz0 = sz1; sz1 = t;
    }
    int Bsz = sz0 / (N*N);
    if (Bsz > MAXB) Bsz = MAXB;
    float* out = (float*)d_out;

    const size_t shmem = 4 * TILE * sizeof(float);   // 66,560 B (> 48 KB -> attr)
    cudaFuncSetAttribute(prep_M_kernel,     cudaFuncAttributeMaxDynamicSharedMemorySize, (int)shmem);
    cudaFuncSetAttribute(batch_log_kernel,  cudaFuncAttributeMaxDynamicSharedMemorySize, (int)shmem);
    cudaFuncSetAttribute(update_M_kernel,   cudaFuncAttributeMaxDynamicSharedMemorySize, (int)shmem);
    cudaFuncSetAttribute(final_prep_kernel, cudaFuncAttributeMaxDynamicSharedMemorySize, (int)shmem);
    cudaFuncSetAttribute(apply_kernel,      cudaFuncAttributeMaxDynamicSharedMemorySize, (int)shmem);

    float *pM, *pL, *pScr, *pPart;
    cudaGetSymbolAddress((void**)&pM,    g_M);
    cudaGetSymbolAddress((void**)&pL,    g_L);
    cudaGetSymbolAddress((void**)&pScr,  g_scratch);
    cudaGetSymbolAddress((void**)&pPart, g_partial);

    const int nb1 = (Bsz + 31) / 32;
    const float inv = 1.0f / (float)Bsz;

    // M0 = mean(data)
    reduce32_kernel    <<<nb1, NT>>>(data, pPart, Bsz);
    reduceFinal_kernel <<<16,  NT>>>(pPart, pM, nb1, inv);

    // 5 Karcher iterations
    for (int it = 0; it < 5; ++it) {
        prep_M_kernel    <<<1,   NT, shmem>>>(it > 0 ? 1 : 0);
        batch_log_kernel <<<Bsz, NT, shmem>>>(data, it > 0 ? 1 : 0);
        reduce32_kernel    <<<nb1, NT>>>(pScr, pPart, Bsz);
        reduceFinal_kernel <<<16,  NT>>>(pPart, pL, nb1, inv);
        update_M_kernel  <<<1,   NT, shmem>>>();
    }

    // C = Bs * invsqrtm(M); out = C X C^T
    final_prep_kernel <<<1,   NT, shmem>>>(bias);
    apply_kernel      <<<Bsz, NT, shmem>>>(data, out);
}